// round 12
// baseline (speedup 1.0000x reference)
#include <cuda_runtime.h>
#include <cstdint>

#define NQ   4096          // matrix dim = 4^6
#define RPB  4             // rows (vectors) per CTA
#define NT   1024          // threads per CTA
#define NBLK (4 * NQ / RPB)

// 536 MB complex intermediate: g_wt[b][j][k] = (X U^H)[k][j]  (transposed row-pass result)
static __device__ __align__(16) float2 g_wt[(size_t)4 * NQ * NQ];

#define SMEM_BYTES (RPB * NQ * sizeof(float2) + 8 * sizeof(float) + 49 * sizeof(float2))

__device__ __forceinline__ float2 cmulf2(float2 a, float2 b) {
    return make_float2(a.x * b.x - a.y * b.y, a.x * b.y + a.y * b.x);
}

// tid==0: factored gate params.
//  ang[0]=cos ang[1]=sin of (th0+th1)/2 (merged Rx) ; ang[2]=cos ang[3]=sin of th2/2 (Ryy)
//  ang[4]=th3/2 ang[5]=th4/2 (Rz diagonal phases)
__device__ __forceinline__ void compute_angles(const float* __restrict__ w, float* ang, int tid) {
    if (tid == 0) {
        const float WM = 0.6324555320336759f;   // sqrt(2)/sqrt(5)
        float A = (w[0] + w[1]) * WM * 0.5f;
        ang[0] = cosf(A);
        ang[1] = sinf(A);
        ang[2] = cosf(w[2] * WM * 0.5f);
        ang[3] = sinf(w[2] * WM * 0.5f);
        ang[4] = w[3] * WM * 0.5f;
        ang[5] = w[4] * WM * 0.5f;
    }
}

// etab[sp*7+sq] = exp(i*sgn*(a*(2sp-6)+b*(2sq-6))); Dtot[i] = etab[popc(i&0xAAA)][popc(i&0x555)]
__device__ __forceinline__ void build_etab(const float* ang, float2* etab, int tid, float sgn) {
    if (tid < 49) {
        int sp = tid / 7, sq = tid % 7;
        float phi = ang[4] * (float)(2 * sp - 6) + ang[5] * (float)(2 * sq - 6);
        etab[tid] = make_float2(cosf(phi), sgn * sinf(phi));
    }
}

// 6 radix-4 butterfly stages of kron^6[ Ryy * (Rx kron I) ] over RPB vectors of length NQ.
__device__ __forceinline__ void run_stages(float2* __restrict__ buf,
                                           float c1, float ts1, float c2, float ts2,
                                           int tid) {
    #pragma unroll
    for (int st = 0; st < 6; ++st) {
        const int s = 1 << (2 * st);
        #pragma unroll
        for (int it = 0; it < (RPB * NQ / 4) / NT; ++it) {
            int q = tid + it * NT;          // butterfly id 0..4095
            int r = q >> 10;                // vector index within CTA
            int u = q & 1023;               // butterfly within vector
            int l = u & (s - 1);
            int base = ((u ^ l) << 2) | l;
            float2* p = buf + r * NQ + base;
            float2 x0 = p[0], x1 = p[s], x2 = p[2 * s], x3 = p[3 * s];
            float2 y0, y1, y2, y3;
            y0.x = c1 * x0.x + ts1 * x2.y;  y0.y = c1 * x0.y - ts1 * x2.x;
            y1.x = c1 * x1.x + ts1 * x3.y;  y1.y = c1 * x1.y - ts1 * x3.x;
            y2.x = c1 * x2.x + ts1 * x0.y;  y2.y = c1 * x2.y - ts1 * x0.x;
            y3.x = c1 * x3.x + ts1 * x1.y;  y3.y = c1 * x3.y - ts1 * x1.x;
            float2 z0, z1, z2, z3;
            z0.x = c2 * y0.x - ts2 * y3.y;  z0.y = c2 * y0.y + ts2 * y3.x;
            z1.x = c2 * y1.x + ts2 * y2.y;  z1.y = c2 * y1.y - ts2 * y2.x;
            z2.x = c2 * y2.x + ts2 * y1.y;  z2.y = c2 * y2.y - ts2 * y1.x;
            z3.x = c2 * y3.x - ts2 * y0.y;  z3.y = c2 * y3.y + ts2 * y0.x;
            p[0] = z0; p[s] = z1; p[2 * s] = z2; p[3 * s] = z3;
        }
        __syncthreads();
    }
}

// Pass 1: rows k0..k0+3 of real X -> conj(U)+conj(D) along rows -> transposed into g_wt.
__global__ __launch_bounds__(NT) void quconv_pass1(const float* __restrict__ x,
                                                   const float* __restrict__ w) {
    extern __shared__ float sm[];
    float2* buf = (float2*)sm;
    float* ang = sm + 2 * RPB * NQ;
    float2* etab = (float2*)(ang + 8);
    int tid = threadIdx.x;

    int kg = blockIdx.x * RPB;
    int batch = kg >> 12;
    int k0 = kg & (NQ - 1);

    compute_angles(w, ang, tid);

    const float4* xr = (const float4*)(x + (size_t)(batch * NQ + k0) * NQ);
    #pragma unroll
    for (int r = 0; r < RPB; ++r) {
        float4 v = xr[r * (NQ / 4) + tid];
        float2* d = buf + r * NQ + tid * 4;
        d[0] = make_float2(v.x, 0.f);
        d[1] = make_float2(v.y, 0.f);
        d[2] = make_float2(v.z, 0.f);
        d[3] = make_float2(v.w, 0.f);
    }
    __syncthreads();

    float c1 = ang[0], ts1 = -ang[1];   // conj(U)
    float c2 = ang[2], ts2 = -ang[3];
    build_etab(ang, etab, tid, -1.0f);

    run_stages(buf, c1, ts1, c2, ts2, tid);

    #pragma unroll
    for (int it = 0; it < NQ / NT; ++it) {
        int j = tid + it * NT;
        float2 d = etab[__popc(j & 0xAAA) * 7 + __popc(j & 0x555)];
        float2 w0 = cmulf2(buf[0 * NQ + j], d);
        float2 w1 = cmulf2(buf[1 * NQ + j], d);
        float2 w2 = cmulf2(buf[2 * NQ + j], d);
        float2 w3 = cmulf2(buf[3 * NQ + j], d);
        float4* dst = (float4*)(g_wt + (size_t)(batch * NQ + j) * NQ + k0);
        dst[0] = make_float4(w0.x, w0.y, w1.x, w1.y);
        dst[1] = make_float4(w2.x, w2.y, w3.x, w3.y);
    }
}

// Pass 2: rows of g_wt (= columns of X U^H) -> U + D -> transposed into d_out.
// mode 0: output float32 = REAL PART, 67,108,864 floats (268 MB).
// mode 1: output interleaved complex64, 67,108,864 float2 (536 MB).
__global__ __launch_bounds__(NT) void quconv_pass2(float* __restrict__ outf,
                                                   const float* __restrict__ w,
                                                   int mode) {
    extern __shared__ float sm[];
    float2* buf = (float2*)sm;
    float* ang = sm + 2 * RPB * NQ;
    float2* etab = (float2*)(ang + 8);
    int tid = threadIdx.x;

    int jg = blockIdx.x * RPB;
    int batch = jg >> 12;
    int j0 = jg & (NQ - 1);

    compute_angles(w, ang, tid);

    const float4* wr = (const float4*)(g_wt + (size_t)(batch * NQ + j0) * NQ);
    #pragma unroll
    for (int r = 0; r < RPB; ++r) {
        #pragma unroll
        for (int it = 0; it < (NQ / 2) / NT; ++it) {
            float4 v = wr[r * (NQ / 2) + tid + it * NT];
            float2* d = buf + r * NQ + (tid + it * NT) * 2;
            d[0] = make_float2(v.x, v.y);
            d[1] = make_float2(v.z, v.w);
        }
    }
    __syncthreads();

    float c1 = ang[0], ts1 = ang[1];    // U
    float c2 = ang[2], ts2 = ang[3];
    build_etab(ang, etab, tid, 1.0f);

    run_stages(buf, c1, ts1, c2, ts2, tid);

    #pragma unroll
    for (int it = 0; it < NQ / NT; ++it) {
        int i = tid + it * NT;
        float2 d = etab[__popc(i & 0xAAA) * 7 + __popc(i & 0x555)];
        float2 w0 = cmulf2(buf[0 * NQ + i], d);
        float2 w1 = cmulf2(buf[1 * NQ + i], d);
        float2 w2 = cmulf2(buf[2 * NQ + i], d);
        float2 w3 = cmulf2(buf[3 * NQ + i], d);
        size_t cidx = (size_t)(batch * NQ + i) * NQ + j0;  // complex element index
        if (mode == 0) {
            // real part only: 4 consecutive floats (j0 % 4 == 0 -> 16B aligned)
            *(float4*)(outf + cidx) = make_float4(w0.x, w1.x, w2.x, w3.x);
        } else {
            float4* dst = (float4*)((float2*)outf + cidx);
            dst[0] = make_float4(w0.x, w0.y, w1.x, w1.y);
            dst[1] = make_float4(w2.x, w2.y, w3.x, w3.y);
        }
    }
}

extern "C" void kernel_launch(void* const* d_in, const int* in_sizes, int n_in,
                              void* d_out, int out_size) {
    // Order-agnostic input selection: largest buffer = x, the other = weight (5 floats).
    int xi = 0;
    for (int i = 0; i < n_in; ++i)
        if (in_sizes[i] > in_sizes[xi]) xi = i;
    int wi = (xi == 0 && n_in > 1) ? 1 : 0;
    const float* x = (const float*)d_in[xi];
    const float* w = (const float*)d_in[wi];

    // Output matrix has 4*4096*4096 = 67,108,864 complex entries.
    //   out_size == 67,108,864  -> float32 buffer  -> REAL PART only (mode 0)
    //   out_size >= 134,217,728 -> room for pairs  -> interleaved complex64 (mode 1)
    int mode = (out_size < 134217728) ? 0 : 1;

    cudaFuncSetAttribute(quconv_pass1, cudaFuncAttributeMaxDynamicSharedMemorySize, (int)SMEM_BYTES);
    cudaFuncSetAttribute(quconv_pass2, cudaFuncAttributeMaxDynamicSharedMemorySize, (int)SMEM_BYTES);

    quconv_pass1<<<NBLK, NT, SMEM_BYTES>>>(x, w);
    quconv_pass2<<<NBLK, NT, SMEM_BYTES>>>((float*)d_out, w, mode);
}

// round 16
// speedup vs baseline: 1.2660x; 1.2660x over previous
#include <cuda_runtime.h>
#include <cstdint>

#define NQ    4096         // matrix dim = 4^6
#define RPB   4            // vectors per CTA
#define NT    1024         // threads per CTA
#define NBLK  (4 * NQ / RPB)
#define PADV  4352         // padded vector stride: 4096 + 4096/16
#define WM    0.6324555320336759f   // sqrt(2)/sqrt(5)

// 536 MB complex intermediate: g_wt[b][j][k] = (X U^H)[k][j]
static __device__ __align__(16) float2 g_wt[(size_t)4 * NQ * NQ];

#define SMEM_BYTES (RPB * PADV * sizeof(float2) + 49 * sizeof(float2))

__device__ __forceinline__ float2 cmulf2(float2 a, float2 b) {
    return make_float2(a.x * b.x - a.y * b.y, a.x * b.y + a.y * b.x);
}

// One radix-4 butterfly of Ryy*(Rx kron I), in place.
__device__ __forceinline__ void r4(float2& x0, float2& x1, float2& x2, float2& x3,
                                   float c1, float ts1, float c2, float ts2) {
    float2 y0, y1, y2, y3;
    y0.x = c1 * x0.x + ts1 * x2.y;  y0.y = c1 * x0.y - ts1 * x2.x;
    y1.x = c1 * x1.x + ts1 * x3.y;  y1.y = c1 * x1.y - ts1 * x3.x;
    y2.x = c1 * x2.x + ts1 * x0.y;  y2.y = c1 * x2.y - ts1 * x0.x;
    y3.x = c1 * x3.x + ts1 * x1.y;  y3.y = c1 * x3.y - ts1 * x1.x;
    x0.x = c2 * y0.x - ts2 * y3.y;  x0.y = c2 * y0.y + ts2 * y3.x;
    x1.x = c2 * y1.x + ts2 * y2.y;  x1.y = c2 * y1.y - ts2 * y2.x;
    x2.x = c2 * y2.x + ts2 * y1.y;  x2.y = c2 * y2.y - ts2 * y1.x;
    x3.x = c2 * y3.x - ts2 * y0.y;  x3.y = c2 * y3.y + ts2 * y0.x;
}

// Radix-16 = two fused radix-4 stages (stride s, then 4s) on 16 register-resident
// elements v[m] = elem(base + m*s). Inner quads {4a..4a+3}, outer {b, b+4, b+8, b+12}.
__device__ __forceinline__ void bfly16(float2* v, float c1, float ts1, float c2, float ts2) {
    #pragma unroll
    for (int a = 0; a < 4; ++a)
        r4(v[4 * a], v[4 * a + 1], v[4 * a + 2], v[4 * a + 3], c1, ts1, c2, ts2);
    #pragma unroll
    for (int b = 0; b < 4; ++b)
        r4(v[b], v[b + 4], v[b + 8], v[b + 12], c1, ts1, c2, ts2);
}

// etab[sp*7+sq] = exp(i*sgn*(a*(2sp-6)+b*(2sq-6))); Dtot[i] = etab[popc(i&0xAAA)][popc(i&0x555)]
__device__ __forceinline__ void build_etab(const float* __restrict__ w, float2* etab,
                                           int tid, float sgn) {
    if (tid < 49) {
        float a = w[3] * WM * 0.5f, b = w[4] * WM * 0.5f;
        int sp = tid / 7, sq = tid % 7;
        float phi = a * (float)(2 * sp - 6) + b * (float)(2 * sq - 6);
        etab[tid] = make_float2(cosf(phi), sgn * sinf(phi));
    }
}

// Pass 1: rows k0..k0+3 of real X -> conj(U)+conj(D) along rows -> transposed into g_wt.
__global__ __launch_bounds__(NT) void quconv_pass1(const float* __restrict__ x,
                                                   const float* __restrict__ w) {
    extern __shared__ float2 smx[];
    float2* buf  = smx;                 // RPB * PADV
    float2* etab = smx + RPB * PADV;    // 49

    const int tid = threadIdx.x;
    const int r = tid >> 8;             // vector 0..3 (constant within a warp)
    const int u = tid & 255;            // butterfly id 0..255
    const int kg = blockIdx.x * RPB;
    const int batch = kg >> 12;
    const int k0 = kg & (NQ - 1);

    // Per-thread gate coefficients (conjugated: sgn = -1).
    float A  = (w[0] + w[1]) * WM * 0.5f;
    float c1 = cosf(A),              ts1 = -sinf(A);
    float c2 = cosf(w[2] * WM * 0.5f), ts2 = -sinf(w[2] * WM * 0.5f);
    build_etab(w, etab, tid, -1.0f);

    float2 v[16];

    // Level 0 fused with global load: 16 consecutive reals.
    {
        const float4* xr = (const float4*)(x + (size_t)(batch * NQ + k0 + r) * NQ + u * 16);
        #pragma unroll
        for (int i = 0; i < 4; ++i) {
            float4 t = xr[i];
            v[4 * i + 0] = make_float2(t.x, 0.f);
            v[4 * i + 1] = make_float2(t.y, 0.f);
            v[4 * i + 2] = make_float2(t.z, 0.f);
            v[4 * i + 3] = make_float2(t.w, 0.f);
        }
        bfly16(v, c1, ts1, c2, ts2);
        float2* b0 = buf + r * PADV + u * 17;      // pad(u*16+m) = u*17+m
        #pragma unroll
        for (int m = 0; m < 16; ++m) b0[m] = v[m];
    }
    __syncthreads();

    // Level 1: stride 16 (padded 17).
    {
        float2* b1 = buf + r * PADV + (u >> 4) * 272 + (u & 15);
        #pragma unroll
        for (int m = 0; m < 16; ++m) v[m] = b1[17 * m];
        bfly16(v, c1, ts1, c2, ts2);
        #pragma unroll
        for (int m = 0; m < 16; ++m) b1[17 * m] = v[m];
    }
    __syncthreads();

    // Level 2: stride 256 (padded 272), diagonal folded into the store.
    {
        float2* b2 = buf + r * PADV + u + (u >> 4);
        #pragma unroll
        for (int m = 0; m < 16; ++m) v[m] = b2[272 * m];
        bfly16(v, c1, ts1, c2, ts2);
        #pragma unroll
        for (int m = 0; m < 16; ++m) {
            int j = u + (m << 8);
            float2 d = etab[__popc(j & 0xAAA) * 7 + __popc(j & 0x555)];
            b2[272 * m] = cmulf2(v[m], d);
        }
    }
    __syncthreads();

    // Transposed write: g_wt[b][j][k0..k0+3], 32B per thread per j.
    #pragma unroll
    for (int it = 0; it < NQ / NT; ++it) {
        int j = tid + it * NT;
        int pj = j + (j >> 4);
        float2 w0 = buf[0 * PADV + pj];
        float2 w1 = buf[1 * PADV + pj];
        float2 w2 = buf[2 * PADV + pj];
        float2 w3 = buf[3 * PADV + pj];
        float4* dst = (float4*)(g_wt + (size_t)(batch * NQ + j) * NQ + k0);
        dst[0] = make_float4(w0.x, w0.y, w1.x, w1.y);
        dst[1] = make_float4(w2.x, w2.y, w3.x, w3.y);
    }
}

// Pass 2: rows of g_wt -> U + D -> transposed into d_out (mode 0 = real part).
__global__ __launch_bounds__(NT) void quconv_pass2(float* __restrict__ outf,
                                                   const float* __restrict__ w,
                                                   int mode) {
    extern __shared__ float2 smx[];
    float2* buf  = smx;
    float2* etab = smx + RPB * PADV;

    const int tid = threadIdx.x;
    const int r = tid >> 8;
    const int u = tid & 255;
    const int jg = blockIdx.x * RPB;
    const int batch = jg >> 12;
    const int j0 = jg & (NQ - 1);

    float A  = (w[0] + w[1]) * WM * 0.5f;
    float c1 = cosf(A),              ts1 = sinf(A);
    float c2 = cosf(w[2] * WM * 0.5f), ts2 = sinf(w[2] * WM * 0.5f);
    build_etab(w, etab, tid, 1.0f);

    float2 v[16];

    // Level 0 fused with global load: 16 consecutive complex.
    {
        const float4* wr = (const float4*)(g_wt + (size_t)(batch * NQ + j0 + r) * NQ + u * 16);
        #pragma unroll
        for (int i = 0; i < 8; ++i) {
            float4 t = wr[i];
            v[2 * i + 0] = make_float2(t.x, t.y);
            v[2 * i + 1] = make_float2(t.z, t.w);
        }
        bfly16(v, c1, ts1, c2, ts2);
        float2* b0 = buf + r * PADV + u * 17;
        #pragma unroll
        for (int m = 0; m < 16; ++m) b0[m] = v[m];
    }
    __syncthreads();

    // Level 1.
    {
        float2* b1 = buf + r * PADV + (u >> 4) * 272 + (u & 15);
        #pragma unroll
        for (int m = 0; m < 16; ++m) v[m] = b1[17 * m];
        bfly16(v, c1, ts1, c2, ts2);
        #pragma unroll
        for (int m = 0; m < 16; ++m) b1[17 * m] = v[m];
    }
    __syncthreads();

    // Level 2 + diagonal.
    {
        float2* b2 = buf + r * PADV + u + (u >> 4);
        #pragma unroll
        for (int m = 0; m < 16; ++m) v[m] = b2[272 * m];
        bfly16(v, c1, ts1, c2, ts2);
        #pragma unroll
        for (int m = 0; m < 16; ++m) {
            int i = u + (m << 8);
            float2 d = etab[__popc(i & 0xAAA) * 7 + __popc(i & 0x555)];
            b2[272 * m] = cmulf2(v[m], d);
        }
    }
    __syncthreads();

    // Transposed write into output.
    #pragma unroll
    for (int it = 0; it < NQ / NT; ++it) {
        int i = tid + it * NT;
        int pi = i + (i >> 4);
        float2 w0 = buf[0 * PADV + pi];
        float2 w1 = buf[1 * PADV + pi];
        float2 w2 = buf[2 * PADV + pi];
        float2 w3 = buf[3 * PADV + pi];
        size_t cidx = (size_t)(batch * NQ + i) * NQ + j0;
        if (mode == 0) {
            // float32 output buffer: REAL PART only (verified convention).
            *(float4*)(outf + cidx) = make_float4(w0.x, w1.x, w2.x, w3.x);
        } else {
            float4* dst = (float4*)((float2*)outf + cidx);
            dst[0] = make_float4(w0.x, w0.y, w1.x, w1.y);
            dst[1] = make_float4(w2.x, w2.y, w3.x, w3.y);
        }
    }
}

extern "C" void kernel_launch(void* const* d_in, const int* in_sizes, int n_in,
                              void* d_out, int out_size) {
    // Order-agnostic input selection: largest buffer = x, the other = weight (5 floats).
    int xi = 0;
    for (int i = 0; i < n_in; ++i)
        if (in_sizes[i] > in_sizes[xi]) xi = i;
    int wi = (xi == 0 && n_in > 1) ? 1 : 0;
    const float* x = (const float*)d_in[xi];
    const float* w = (const float*)d_in[wi];

    int mode = (out_size < 134217728) ? 0 : 1;   // 67M floats -> real-part output

    cudaFuncSetAttribute(quconv_pass1, cudaFuncAttributeMaxDynamicSharedMemorySize, (int)SMEM_BYTES);
    cudaFuncSetAttribute(quconv_pass2, cudaFuncAttributeMaxDynamicSharedMemorySize, (int)SMEM_BYTES);

    quconv_pass1<<<NBLK, NT, SMEM_BYTES>>>(x, w);
    quconv_pass2<<<NBLK, NT, SMEM_BYTES>>>((float*)d_out, w, mode);
}